// round 12
// baseline (speedup 1.0000x reference)
#include <cuda_runtime.h>
#include <cstdint>
#include <math.h>

#define NUM_BINS 16
#define BOUND 3.0f
#define MIN_BIN_WIDTH 0.001f
#define MIN_BIN_HEIGHT 0.001f
#define MIN_DERIVATIVE 0.001f
#define MIN_LAMBDA 0.025f
#define EPS_C 1e-6f

#define TPB 64
#define TILE 64
#define P 63
#define TILE_FLOATS (TILE * P)        // 4032 floats
#define TILE_BYTES  (TILE_FLOATS * 4) // 16128 B, 16B-multiple; tile gmem base also 16B-aligned

__device__ __forceinline__ void mbar_init(uint32_t mb, uint32_t count) {
    asm volatile("mbarrier.init.shared.b64 [%0], %1;" :: "r"(mb), "r"(count) : "memory");
}
__device__ __forceinline__ void mbar_expect_tx(uint32_t mb, uint32_t bytes) {
    asm volatile("mbarrier.arrive.expect_tx.shared.b64 _, [%0], %1;" :: "r"(mb), "r"(bytes) : "memory");
}
__device__ __forceinline__ void bulk_g2s(uint32_t sdst, const void* gsrc, uint32_t bytes, uint32_t mb) {
    asm volatile("cp.async.bulk.shared::cluster.global.mbarrier::complete_tx::bytes [%0], [%1], %2, [%3];"
                 :: "r"(sdst), "l"(gsrc), "r"(bytes), "r"(mb) : "memory");
}
__device__ __forceinline__ void mbar_wait(uint32_t mb, uint32_t parity) {
    uint32_t done;
    asm volatile("{\n\t.reg .pred p;\n\t"
                 "mbarrier.try_wait.parity.acquire.cta.shared::cta.b64 p, [%1], %2;\n\t"
                 "selp.b32 %0, 1, 0, p;\n\t}"
                 : "=r"(done) : "r"(mb), "r"(parity) : "memory");
    if (!done) {
        asm volatile("{\n\t.reg .pred P1;\n\t"
                     "WL_%=:\n\t"
                     "mbarrier.try_wait.parity.acquire.cta.shared::cta.b64 P1, [%0], %1, 0x989680;\n\t"
                     "@P1 bra.uni WD_%=;\n\t"
                     "bra.uni WL_%=;\n\t"
                     "WD_%=:\n\t}"
                     :: "r"(mb), "r"(parity) : "memory");
    }
}

__global__ __launch_bounds__(TPB) void lrs_kernel(
    const float* __restrict__ inputs,
    const float* __restrict__ params,
    float* __restrict__ out,
    int n, int ntiles)
{
    __shared__ alignas(128) float sm[2][TILE_FLOATS];   // 2 * 16128 B
    __shared__ alignas(8) unsigned long long mbar_s[2];

    const int tid = threadIdx.x;
    const int G = gridDim.x;
    const uint32_t mb[2] = { (uint32_t)__cvta_generic_to_shared(&mbar_s[0]),
                             (uint32_t)__cvta_generic_to_shared(&mbar_s[1]) };
    const uint32_t sbuf[2] = { (uint32_t)__cvta_generic_to_shared(&sm[0][0]),
                               (uint32_t)__cvta_generic_to_shared(&sm[1][0]) };

    if (tid == 0) { mbar_init(mb[0], 1); mbar_init(mb[1], 1); }
    __syncthreads();

    // single-thread, single-instruction tile stage (only for full tiles)
    auto stage = [&](int t, int b) {
        if (tid == 0) {
            mbar_expect_tx(mb[b], TILE_BYTES);
            bulk_g2s(sbuf[b], params + (size_t)(t * TILE) * P, TILE_BYTES, mb[b]);
        }
    };

    const int t0 = blockIdx.x;
    bool staged[2] = { false, false };
    int  use[2]    = { 0, 0 };           // per-buffer use counter -> parity

    if (t0 < ntiles && (t0 + 1) * TILE <= n) { stage(t0, 0); staged[0] = true; }

    int j = 0;
    for (int t = t0; t < ntiles; t += G, j++) {
        const int b = j & 1;
        const int tn = t + G;
        if (tn < ntiles && (tn + 1) * TILE <= n) {   // prefetch next tile into other buffer
            stage(tn, b ^ 1);
            staged[b ^ 1] = true;
        }
        const bool full = staged[b];
        if (full) { mbar_wait(mb[b], use[b] & 1); use[b]++; staged[b] = false; }

        const int elem = t * TILE + tid;
        if (elem < n) {
            const float* mp = &sm[b][tid * P];                // stride 63: conflict-free
            const float* grow = params + (size_t)elem * P;    // ragged fallback
            const float x = __ldg(inputs + elem);

            // ========== widths softmax (register-resident, no max-sub) ==========
            float ew[NUM_BINS];
            float s = 0.0f;
            #pragma unroll
            for (int k = 0; k < NUM_BINS; k++) {
                float wr = full ? mp[k] : __ldg(grow + k);
                ew[k] = __expf(wr); s += ew[k];
            }
            const float wscale = (1.0f - MIN_BIN_WIDTH * NUM_BINS) * __fdividef(1.0f, s);

            int cnt = (x >= -BOUND + EPS_C) ? 1 : 0;
            float cwL = -BOUND, cwR = BOUND;
            bool haveR = false;
            {
                float cum = 0.0f;
                #pragma unroll
                for (int k = 0; k < NUM_BINS; k++) {
                    cum += fmaf(wscale, ew[k], MIN_BIN_WIDTH);
                    float knot = (k == NUM_BINS - 1) ? BOUND : fmaf(cum, 2.0f * BOUND, -BOUND);
                    if (x >= knot + EPS_C) { cnt++; cwL = knot; }
                    else if (!haveR)       { haveR = true; cwR = knot; }
                }
            }
            const int bin = min(max(cnt - 1, 0), NUM_BINS - 1);
            const float in_w = cwR - cwL;

            // d/lam from smem (staged full row)
            const float dLraw  = full ? mp[(2 * NUM_BINS - 1) + bin] : __ldg(grow + (2 * NUM_BINS - 1) + bin);
            const float dRraw  = full ? mp[2 * NUM_BINS + bin]       : __ldg(grow + 2 * NUM_BINS + bin);
            const float lamraw = full ? mp[(3 * NUM_BINS - 1) + bin] : __ldg(grow + (3 * NUM_BINS - 1) + bin);

            // ========== heights softmax ==========
            float eh[NUM_BINS];
            float sh = 0.0f;
            #pragma unroll
            for (int k = 0; k < NUM_BINS; k++) {
                float hr = full ? mp[NUM_BINS + k] : __ldg(grow + NUM_BINS + k);
                eh[k] = __expf(hr); sh += eh[k];
            }
            const float hscale = (1.0f - MIN_BIN_HEIGHT * NUM_BINS) * __fdividef(1.0f, sh);

            float chL = -BOUND, chR = BOUND;
            {
                float cum = 0.0f;
                #pragma unroll
                for (int k = 0; k < NUM_BINS; k++) {
                    cum += fmaf(hscale, eh[k], MIN_BIN_HEIGHT);
                    float knot = (k == NUM_BINS - 1) ? BOUND : fmaf(cum, 2.0f * BOUND, -BOUND);
                    if (k + 1 == bin) chL = knot;
                    if (k == bin)     chR = knot;
                }
            }
            const float in_h = chR - chL;

            // ========== derivatives (2 softplus) + lambda (1 sigmoid) ==========
            const float edge = 1.0f - MIN_DERIVATIVE;
            float dL, dR;
            if (bin > 0)
                dL = MIN_DERIVATIVE + fmaxf(dLraw, 0.0f) + __logf(1.0f + __expf(-fabsf(dLraw)));
            else dL = edge;
            if (bin < NUM_BINS - 1)
                dR = MIN_DERIVATIVE + fmaxf(dRraw, 0.0f) + __logf(1.0f + __expf(-fabsf(dRraw)));
            else dR = edge;

            const float sig = __fdividef(1.0f, 1.0f + __expf(-lamraw));
            const float lam = fmaf(1.0f - 2.0f * MIN_LAMBDA, sig, MIN_LAMBDA);

            // ========== spline evaluation ==========
            const float r_inw = __fdividef(1.0f, in_w);
            const float r_inh = __fdividef(1.0f, in_h);
            const float wb  = sqrtf(__fdividef(dL, dR));
            const float lwb = lam * wb;
            const float wc  = (lam * dL + (wb - lwb) * dR) * in_w * r_inh;
            const float ya  = chL;
            const float yb  = in_h + chL;
            const float l1  = 1.0f - lam;
            const float yc  = __fdividef(lwb * yb + l1 * ya, l1 + lwb);

            const float theta  = (x - cwL) * r_inw;
            const bool  ind    = theta <= lam;
            const float ltheta = lam - theta;
            const float wcyc   = wc * yc;
            const float wcyctheta = wcyc * theta;
            const float wbyb   = wb * yb;
            const float numerator   = ind ? (wcyctheta + ya * ltheta)
                                          : ((wcyc - wcyctheta) - wbyb * ltheta);
            const float wctheta = wc * theta;
            const float denominator = ind ? (wctheta + ltheta)
                                          : ((wc - wctheta) - wb * ltheta);
            const float rden   = __fdividef(1.0f, denominator);
            const float result = numerator * rden;

            const float dnum = wc * (ind ? (lam * (yc - ya)) : ((wb - lwb) * (yb - yc))) * r_inw;
            const float lad  = __logf(dnum * rden * rden);

            const bool outside = (x < -BOUND) || (x > BOUND);
            out[elem]     = outside ? x : result;
            out[n + elem] = outside ? 0.0f : lad;
        }
        __syncthreads();   // all reads of buf b done before tid0 re-stages it next iter
    }
}

extern "C" void kernel_launch(void* const* d_in, const int* in_sizes, int n_in,
                              void* d_out, int out_size) {
    const float* inputs = (const float*)d_in[0];
    const float* params = (const float*)d_in[1];
    float* out = (float*)d_out;
    int n = in_sizes[0];
    int ntiles = (n + TILE - 1) / TILE;
    int grid = 152 * 7;               // persistent: 7 CTAs/SM
    if (grid > ntiles) grid = ntiles;
    lrs_kernel<<<grid, TPB>>>(inputs, params, out, n, ntiles);
}